// round 2
// baseline (speedup 1.0000x reference)
#include <cuda_runtime.h>
#include <math_constants.h>

// RoiMaxPooling: x (256,56,56,256) f32 NHWC -> adaptive 7x7 max pool (8x8 bins)
// with the reference's transpose/reshape index scramble:
//   out_linear_row = w*(7*B) + h*B + b
//
// R2: occupancy push. 4-load reduction groups (half the live regs of the
// 8-wide tree) + __launch_bounds__(256,4) -> 4 CTAs/SM, 32 warps, doubling
// SM-level outstanding-load count to close the remaining 11% DRAM idle.

#define B_   256
#define HH   56
#define WW   56
#define CC   256
#define GH   7
#define GW   7

__device__ __forceinline__ float4 vmax4(float4 a, float4 b) {
    return make_float4(fmaxf(a.x, b.x), fmaxf(a.y, b.y),
                       fmaxf(a.z, b.z), fmaxf(a.w, b.w));
}

__global__ __launch_bounds__(256, 4)
void roi_maxpool_kernel(const float4* __restrict__ x, float4* __restrict__ out) {
    // 4 bins per 256-thread block; 64 threads per bin; 4 channels (float4) per thread.
    const int t    = threadIdx.x;
    const int bin  = (blockIdx.x << 2) + (t >> 6);   // 0 .. 256*49-1
    const int lane = t & 63;                          // channel-group 0..63

    const int b  = bin / (GH * GW);
    const int hw = bin - b * (GH * GW);
    const int h  = hw / GW;
    const int w  = hw - h * GW;

    const int C4  = CC / 4;        // 64 float4 per pixel
    const int ROW = WW * C4;       // float4 per H-row (3584)

    // base pixel of this 8x8 window
    const int base = ((b * HH + h * 8) * WW + w * 8) * C4 + lane;

    float4 acc = make_float4(-CUDART_INF_F, -CUDART_INF_F,
                             -CUDART_INF_F, -CUDART_INF_F);

    #pragma unroll
    for (int i = 0; i < 8; i++) {
        const float4* rp = x + base + i * ROW;
        // group 1: 4 independent LDG.128
        {
            float4 v0 = __ldg(rp + 0 * C4);
            float4 v1 = __ldg(rp + 1 * C4);
            float4 v2 = __ldg(rp + 2 * C4);
            float4 v3 = __ldg(rp + 3 * C4);
            acc = vmax4(acc, vmax4(vmax4(v0, v1), vmax4(v2, v3)));
        }
        // group 2: 4 independent LDG.128
        {
            float4 v4 = __ldg(rp + 4 * C4);
            float4 v5 = __ldg(rp + 5 * C4);
            float4 v6 = __ldg(rp + 6 * C4);
            float4 v7 = __ldg(rp + 7 * C4);
            acc = vmax4(acc, vmax4(vmax4(v4, v5), vmax4(v6, v7)));
        }
    }

    // Scrambled destination: linear row = w*(GH*B) + h*B + b
    const int orow = (w * (GH * B_) + h * B_ + b);
    out[orow * C4 + lane] = acc;
}

extern "C" void kernel_launch(void* const* d_in, const int* in_sizes, int n_in,
                              void* d_out, int out_size) {
    const float4* x = (const float4*)d_in[0];
    float4* out = (float4*)d_out;
    const int n_bins = B_ * GH * GW;          // 12544
    const int blocks = n_bins / 4;            // 3136
    roi_maxpool_kernel<<<blocks, 256>>>(x, out);
}

// round 3
// speedup vs baseline: 1.0021x; 1.0021x over previous
#include <cuda_runtime.h>
#include <math_constants.h>

// RoiMaxPooling: x (256,56,56,256) f32 NHWC -> adaptive 7x7 max pool (8x8 bins)
// with the reference's transpose/reshape index scramble:
//   out_linear_row = w*(7*B) + h*B + b
//
// R3: R1's deep-MLP structure (full 8x8 unroll, 8-wide tree -> ptxas
// software-pipelines loads across rows) but register-capped to 3 CTAs/SM:
// intermediate point on the (per-thread MLP) x (warp count) tradeoff.
// R1: {MLP~24, 16w} -> 88.6% DRAM. R2: {MLP~8, 32w} -> 86.3%.

#define B_   256
#define HH   56
#define WW   56
#define CC   256
#define GH   7
#define GW   7

__device__ __forceinline__ float4 vmax4(float4 a, float4 b) {
    return make_float4(fmaxf(a.x, b.x), fmaxf(a.y, b.y),
                       fmaxf(a.z, b.z), fmaxf(a.w, b.w));
}

__global__ __launch_bounds__(256, 3)
void roi_maxpool_kernel(const float4* __restrict__ x, float4* __restrict__ out) {
    // 4 bins per 256-thread block; 64 threads per bin; 4 channels (float4) per thread.
    const int t    = threadIdx.x;
    const int bin  = (blockIdx.x << 2) + (t >> 6);   // 0 .. 256*49-1
    const int lane = t & 63;                          // channel-group 0..63

    const int b  = bin / (GH * GW);
    const int hw = bin - b * (GH * GW);
    const int h  = hw / GW;
    const int w  = hw - h * GW;

    const int C4  = CC / 4;        // 64 float4 per pixel
    const int ROW = WW * C4;       // float4 per H-row (3584)

    // base pixel of this 8x8 window
    const int base = ((b * HH + h * 8) * WW + w * 8) * C4 + lane;

    float4 acc = make_float4(-CUDART_INF_F, -CUDART_INF_F,
                             -CUDART_INF_F, -CUDART_INF_F);

    #pragma unroll
    for (int i = 0; i < 8; i++) {
        const float4* rp = x + base + i * ROW;
        // 8 independent LDG.128 per row, tree-reduced; ptxas pipelines
        // across rows up to the 3-CTA register budget (~84 regs).
        float4 v0 = __ldg(rp + 0 * C4);
        float4 v1 = __ldg(rp + 1 * C4);
        float4 v2 = __ldg(rp + 2 * C4);
        float4 v3 = __ldg(rp + 3 * C4);
        float4 v4 = __ldg(rp + 4 * C4);
        float4 v5 = __ldg(rp + 5 * C4);
        float4 v6 = __ldg(rp + 6 * C4);
        float4 v7 = __ldg(rp + 7 * C4);
        float4 a01 = vmax4(v0, v1);
        float4 a23 = vmax4(v2, v3);
        float4 a45 = vmax4(v4, v5);
        float4 a67 = vmax4(v6, v7);
        float4 a03 = vmax4(a01, a23);
        float4 a47 = vmax4(a45, a67);
        acc = vmax4(acc, vmax4(a03, a47));
    }

    // Scrambled destination: linear row = w*(GH*B) + h*B + b
    const int orow = (w * (GH * B_) + h * B_ + b);
    out[orow * C4 + lane] = acc;
}

extern "C" void kernel_launch(void* const* d_in, const int* in_sizes, int n_in,
                              void* d_out, int out_size) {
    const float4* x = (const float4*)d_in[0];
    float4* out = (float4*)d_out;
    const int n_bins = B_ * GH * GW;          // 12544
    const int blocks = n_bins / 4;            // 3136
    roi_maxpool_kernel<<<blocks, 256>>>(x, out);
}

// round 4
// speedup vs baseline: 1.0053x; 1.0032x over previous
#include <cuda_runtime.h>
#include <math_constants.h>

// RoiMaxPooling: x (256,56,56,256) f32 NHWC -> adaptive 7x7 max pool (8x8 bins)
// with the reference's transpose/reshape index scramble:
//   out_linear_row = w*(7*B) + h*B + b
//
// R4: R3 structure (deep 8-wide tree, 3 CTAs/SM) + streaming cache hints.
// Input is read exactly once (822 MB >> 126 MB L2) and output written once:
// __ldcs/__stcs (evict-first) stops the LTS from retaining dead lines.

#define B_   256
#define HH   56
#define WW   56
#define CC   256
#define GH   7
#define GW   7

__device__ __forceinline__ float4 vmax4(float4 a, float4 b) {
    return make_float4(fmaxf(a.x, b.x), fmaxf(a.y, b.y),
                       fmaxf(a.z, b.z), fmaxf(a.w, b.w));
}

__global__ __launch_bounds__(256, 3)
void roi_maxpool_kernel(const float4* __restrict__ x, float4* __restrict__ out) {
    // 4 bins per 256-thread block; 64 threads per bin; 4 channels (float4) per thread.
    const int t    = threadIdx.x;
    const int bin  = (blockIdx.x << 2) + (t >> 6);   // 0 .. 256*49-1
    const int lane = t & 63;                          // channel-group 0..63

    const int b  = bin / (GH * GW);
    const int hw = bin - b * (GH * GW);
    const int h  = hw / GW;
    const int w  = hw - h * GW;

    const int C4  = CC / 4;        // 64 float4 per pixel
    const int ROW = WW * C4;       // float4 per H-row (3584)

    // base pixel of this 8x8 window
    const int base = ((b * HH + h * 8) * WW + w * 8) * C4 + lane;

    float4 acc = make_float4(-CUDART_INF_F, -CUDART_INF_F,
                             -CUDART_INF_F, -CUDART_INF_F);

    #pragma unroll
    for (int i = 0; i < 8; i++) {
        const float4* rp = x + base + i * ROW;
        // 8 independent streaming LDG.128 per row, tree-reduced; ptxas
        // pipelines across rows up to the 3-CTA register budget.
        float4 v0 = __ldcs(rp + 0 * C4);
        float4 v1 = __ldcs(rp + 1 * C4);
        float4 v2 = __ldcs(rp + 2 * C4);
        float4 v3 = __ldcs(rp + 3 * C4);
        float4 v4 = __ldcs(rp + 4 * C4);
        float4 v5 = __ldcs(rp + 5 * C4);
        float4 v6 = __ldcs(rp + 6 * C4);
        float4 v7 = __ldcs(rp + 7 * C4);
        float4 a01 = vmax4(v0, v1);
        float4 a23 = vmax4(v2, v3);
        float4 a45 = vmax4(v4, v5);
        float4 a67 = vmax4(v6, v7);
        float4 a03 = vmax4(a01, a23);
        float4 a47 = vmax4(a45, a67);
        acc = vmax4(acc, vmax4(a03, a47));
    }

    // Scrambled destination: linear row = w*(GH*B) + h*B + b
    const int orow = (w * (GH * B_) + h * B_ + b);
    __stcs(out + orow * C4 + lane, acc);
}

extern "C" void kernel_launch(void* const* d_in, const int* in_sizes, int n_in,
                              void* d_out, int out_size) {
    const float4* x = (const float4*)d_in[0];
    float4* out = (float4*)d_out;
    const int n_bins = B_ * GH * GW;          // 12544
    const int blocks = n_bins / 4;            // 3136
    roi_maxpool_kernel<<<blocks, 256>>>(x, out);
}